// round 1
// baseline (speedup 1.0000x reference)
#include <cuda_runtime.h>

// Encoder: out[b,e] = relu( sum_i combined[b,i] * weight[b,i,e] )
// combined = [ features[nodes[b]] , mean_j features[neigh_idx[b,j]] ]  (256 dims)
// Shapes: features [100000,128] f32, weight [4096,256,128] f32,
//         nodes [4096] i32, neigh_idx [4096,10] i32, out [4096,128] f32.

#define FEAT 128
#define EMBED 128
#define TWO_FEAT 256
#define NUM_SAMPLE 10

__global__ __launch_bounds__(128, 8)
void encoder_kernel(const float* __restrict__ features,
                    const float* __restrict__ weight,
                    const int*   __restrict__ nodes,
                    const int*   __restrict__ neigh,
                    float*       __restrict__ out)
{
    __shared__ float comb[TWO_FEAT];
    __shared__ float part[4][EMBED];

    const int b = blockIdx.x;
    const int t = threadIdx.x;          // 0..127

    // ---- Phase 1: build combined[256] in shared ----
    // thread t owns feature dim t. All row loads are coalesced 512B segments.
    const int node = __ldg(&nodes[b]);
    float self_f = __ldg(&features[(size_t)node * FEAT + t]);

    float msum = 0.0f;
    #pragma unroll
    for (int j = 0; j < NUM_SAMPLE; ++j) {
        const int nb = __ldg(&neigh[b * NUM_SAMPLE + j]);
        msum += __ldg(&features[(size_t)nb * FEAT + t]);
    }
    comb[t]        = self_f;
    comb[FEAT + t] = msum * (1.0f / NUM_SAMPLE);
    __syncthreads();

    // ---- Phase 2: per-sample matvec, streaming weight[b] (128 KB) ----
    // warp w handles rows i in [w*64, w*64+64). lane reads float4 covering
    // e = 4*lane .. 4*lane+3. One warp-iteration = one contiguous 512B row.
    const int warp = t >> 5;
    const int lane = t & 31;

    const float4* __restrict__ Wb =
        reinterpret_cast<const float4*>(weight + (size_t)b * TWO_FEAT * EMBED);

    float4 acc = make_float4(0.f, 0.f, 0.f, 0.f);
    const int i0 = warp * 64;

    #pragma unroll 8
    for (int k = 0; k < 64; ++k) {
        const int i = i0 + k;
        const float  c = comb[i];
        const float4 w = __ldg(&Wb[(size_t)i * (EMBED / 4) + lane]);
        acc.x = fmaf(c, w.x, acc.x);
        acc.y = fmaf(c, w.y, acc.y);
        acc.z = fmaf(c, w.z, acc.z);
        acc.w = fmaf(c, w.w, acc.w);
    }

    // stash per-warp partials
    reinterpret_cast<float4*>(&part[warp][0])[lane] = acc;
    __syncthreads();

    // ---- reduce 4 warps, relu, store (coalesced 512B) ----
    const float v = part[0][t] + part[1][t] + part[2][t] + part[3][t];
    out[(size_t)b * EMBED + t] = fmaxf(v, 0.0f);
}

extern "C" void kernel_launch(void* const* d_in, const int* in_sizes, int n_in,
                              void* d_out, int out_size)
{
    const float* features = (const float*)d_in[0];
    const float* weight   = (const float*)d_in[1];
    const int*   nodes    = (const int*)d_in[2];
    const int*   neigh    = (const int*)d_in[3];
    float*       out      = (float*)d_out;

    const int batch = in_sizes[2];      // 4096 (nodes element count)
    encoder_kernel<<<batch, 128>>>(features, weight, nodes, neigh, out);
}

// round 2
// speedup vs baseline: 1.0286x; 1.0286x over previous
#include <cuda_runtime.h>

// Encoder: out[b,e] = relu( sum_i combined[b,i] * weight[b,i,e] )
// combined = [ features[nodes[b]] , mean_j features[neigh_idx[b,j]] ]  (256 dims)
// Shapes: features [100000,128] f32, weight [4096,256,128] f32,
//         nodes [4096] i32, neigh_idx [4096,10] i32, out [4096,128] f32.
//
// HBM-bound streaming kernel. Key points:
//  - weight (512MB, single-use) is loaded with __ldcs (evict-first) so the
//    51MB feature table stays resident in the 126MB L2 -> gathers hit L2.
//  - per-warp float4 row loads = one contiguous 512B request per iteration.
//  - 4-row register prefetch starts the weight stream before the gather
//    latency chain resolves.

#define FEAT 128
#define EMBED 128
#define TWO_FEAT 256
#define NUM_SAMPLE 10

__global__ __launch_bounds__(128, 8)
void encoder_kernel(const float* __restrict__ features,
                    const float* __restrict__ weight,
                    const int*   __restrict__ nodes,
                    const int*   __restrict__ neigh,
                    float*       __restrict__ out)
{
    __shared__ float comb[TWO_FEAT];
    __shared__ float part[4][EMBED];

    const int b = blockIdx.x;
    const int t = threadIdx.x;          // 0..127
    const int warp = t >> 5;
    const int lane = t & 31;

    const float4* __restrict__ Wb =
        reinterpret_cast<const float4*>(weight + (size_t)b * TWO_FEAT * EMBED);
    const int i0 = warp * 64;

    // ---- start the weight stream immediately (evict-first, it is single-use)
    float4 pre0 = __ldcs(&Wb[(size_t)(i0 + 0) * (EMBED / 4) + lane]);
    float4 pre1 = __ldcs(&Wb[(size_t)(i0 + 1) * (EMBED / 4) + lane]);
    float4 pre2 = __ldcs(&Wb[(size_t)(i0 + 2) * (EMBED / 4) + lane]);
    float4 pre3 = __ldcs(&Wb[(size_t)(i0 + 3) * (EMBED / 4) + lane]);

    // ---- Phase 1: build combined[256] in shared (coalesced 512B row loads,
    //      L2-resident thanks to the streaming hint on weight)
    const int node = __ldg(&nodes[b]);
    float self_f = __ldg(&features[(size_t)node * FEAT + t]);

    float msum = 0.0f;
    #pragma unroll
    for (int j = 0; j < NUM_SAMPLE; ++j) {
        const int nb = __ldg(&neigh[b * NUM_SAMPLE + j]);
        msum += __ldg(&features[(size_t)nb * FEAT + t]);
    }
    comb[t]        = self_f;
    comb[FEAT + t] = msum * (1.0f / NUM_SAMPLE);
    __syncthreads();

    // ---- Phase 2: per-sample matvec, streaming weight[b] (128 KB/CTA)
    // warp w handles rows [w*64, w*64+64); lane covers e = 4*lane..4*lane+3.
    float4 accA = make_float4(0.f, 0.f, 0.f, 0.f);
    float4 accB = make_float4(0.f, 0.f, 0.f, 0.f);

    // consume prefetched rows 0..3
    {
        float c0 = comb[i0 + 0], c1 = comb[i0 + 1];
        float c2 = comb[i0 + 2], c3 = comb[i0 + 3];
        accA.x = fmaf(c0, pre0.x, accA.x); accA.y = fmaf(c0, pre0.y, accA.y);
        accA.z = fmaf(c0, pre0.z, accA.z); accA.w = fmaf(c0, pre0.w, accA.w);
        accB.x = fmaf(c1, pre1.x, accB.x); accB.y = fmaf(c1, pre1.y, accB.y);
        accB.z = fmaf(c1, pre1.z, accB.z); accB.w = fmaf(c1, pre1.w, accB.w);
        accA.x = fmaf(c2, pre2.x, accA.x); accA.y = fmaf(c2, pre2.y, accA.y);
        accA.z = fmaf(c2, pre2.z, accA.z); accA.w = fmaf(c2, pre2.w, accA.w);
        accB.x = fmaf(c3, pre3.x, accB.x); accB.y = fmaf(c3, pre3.y, accB.y);
        accB.z = fmaf(c3, pre3.z, accB.z); accB.w = fmaf(c3, pre3.w, accB.w);
    }

    #pragma unroll 8
    for (int k = 4; k < 64; k += 2) {
        const float  cA = comb[i0 + k];
        const float  cB = comb[i0 + k + 1];
        const float4 wA = __ldcs(&Wb[(size_t)(i0 + k)     * (EMBED / 4) + lane]);
        const float4 wB = __ldcs(&Wb[(size_t)(i0 + k + 1) * (EMBED / 4) + lane]);
        accA.x = fmaf(cA, wA.x, accA.x); accA.y = fmaf(cA, wA.y, accA.y);
        accA.z = fmaf(cA, wA.z, accA.z); accA.w = fmaf(cA, wA.w, accA.w);
        accB.x = fmaf(cB, wB.x, accB.x); accB.y = fmaf(cB, wB.y, accB.y);
        accB.z = fmaf(cB, wB.z, accB.z); accB.w = fmaf(cB, wB.w, accB.w);
    }

    float4 acc;
    acc.x = accA.x + accB.x;
    acc.y = accA.y + accB.y;
    acc.z = accA.z + accB.z;
    acc.w = accA.w + accB.w;

    // stash per-warp partials
    reinterpret_cast<float4*>(&part[warp][0])[lane] = acc;
    __syncthreads();

    // ---- reduce 4 warps, relu, store (coalesced 512B)
    const float v = part[0][t] + part[1][t] + part[2][t] + part[3][t];
    out[(size_t)b * EMBED + t] = fmaxf(v, 0.0f);
}

extern "C" void kernel_launch(void* const* d_in, const int* in_sizes, int n_in,
                              void* d_out, int out_size)
{
    const float* features = (const float*)d_in[0];
    const float* weight   = (const float*)d_in[1];
    const int*   nodes    = (const int*)d_in[2];
    const int*   neigh    = (const int*)d_in[3];
    float*       out      = (float*)d_out;

    const int batch = in_sizes[2];      // 4096 (nodes element count)
    encoder_kernel<<<batch, 128>>>(features, weight, nodes, neigh, out);
}